// round 10
// baseline (speedup 1.0000x reference)
#include <cuda_runtime.h>
#include <cuda_fp16.h>
#include <math.h>
#include <stdint.h>

// Problem constants
#define B_   2
#define S_   2048
#define D_   1024
#define H_   16
#define DK_  64
#define MTOT (B_ * S_)   // 4096
#define WSZ  ((size_t)D_ * D_)

#define WSCALE   64.0f
#define INV_WS   (1.0f / 64.0f)
#define QSCALE   (0.125f * 1.44269504f)   // 1/sqrt(dk) * log2(e)  (softmax in base 2)

// fp16 buffers (all single precision fp16, fp32 accumulate in MMA)
__device__ __half g_xf [(size_t)MTOT * D_];     // X
__device__ __half g_wf [4][WSZ];                // 64*W
__device__ __half g_qf [(size_t)MTOT * D_];     // Q (pre-scaled by QSCALE)
__device__ __half g_kf [(size_t)MTOT * D_];
__device__ __half g_vf [(size_t)MTOT * D_];
__device__ __half g_of [(size_t)MTOT * D_];     // attn out

// ============================================================================
// PTX helpers (base sm_100-safe)
// ============================================================================
__device__ __forceinline__ uint32_t smem_u32(const void* p) {
    return (uint32_t)__cvta_generic_to_shared(p);
}

__device__ __forceinline__ float ex2f(float x) {
    float r;
    asm("ex2.approx.f32 %0, %1;" : "=f"(r) : "f"(x));
    return r;
}

#define CP_ASYNC16(dst, src) \
    asm volatile("cp.async.cg.shared.global [%0], [%1], 16;" :: "r"(dst), "l"(src))
#define CP_COMMIT() asm volatile("cp.async.commit_group;")
#define CP_WAIT1()  asm volatile("cp.async.wait_group 1;")
#define CP_WAIT0()  asm volatile("cp.async.wait_group 0;")

#define LDSM_X4(r, addr)                                                     \
    asm volatile("ldmatrix.sync.aligned.m8n8.x4.shared.b16 {%0,%1,%2,%3}, [%4];" \
                 : "=r"((r)[0]), "=r"((r)[1]), "=r"((r)[2]), "=r"((r)[3])    \
                 : "r"(addr))

#define LDSM_X4_T(r, addr)                                                   \
    asm volatile("ldmatrix.sync.aligned.m8n8.x4.trans.shared.b16 {%0,%1,%2,%3}, [%4];" \
                 : "=r"((r)[0]), "=r"((r)[1]), "=r"((r)[2]), "=r"((r)[3])    \
                 : "r"(addr))

#define MMAH16816(d, a, b0v, b1v)                                            \
    asm volatile("mma.sync.aligned.m16n8k16.row.col.f32.f16.f16.f32 "       \
                 "{%0,%1,%2,%3}, {%4,%5,%6,%7}, {%8,%9}, {%0,%1,%2,%3};"    \
                 : "+f"((d)[0]), "+f"((d)[1]), "+f"((d)[2]), "+f"((d)[3])   \
                 : "r"((a)[0]), "r"((a)[1]), "r"((a)[2]), "r"((a)[3]),      \
                   "r"(b0v), "r"(b1v))

__device__ __forceinline__ uint32_t pack_h2(float a, float b) {
    __half2 h = __floats2half2_rn(a, b);
    return *(uint32_t*)&h;
}

// ============================================================================
// conversion kernels
// ============================================================================
__global__ void cvt_half(const float* __restrict__ src, __half* __restrict__ dst, int n)
{
    int i = (blockIdx.x * blockDim.x + threadIdx.x) * 4;
    if (i >= n) return;
    float4 v = *(const float4*)(src + i);
    uint2 o = make_uint2(pack_h2(v.x, v.y), pack_h2(v.z, v.w));
    *(uint2*)(dst + i) = o;
}

// 4-weight convert with *WSCALE pre-scaling (z selects which W)
__global__ void cvt_w4(const float* __restrict__ W0, const float* __restrict__ W1,
                       const float* __restrict__ W2, const float* __restrict__ W3,
                       __half* __restrict__ dstB)
{
    const int z = blockIdx.z;
    const float* src = (z == 0) ? W0 : (z == 1) ? W1 : (z == 2) ? W2 : W3;
    int i = (blockIdx.x * blockDim.x + threadIdx.x) * 4;
    float4 v = *(const float4*)(src + i);
    uint2 o = make_uint2(pack_h2(v.x * WSCALE, v.y * WSCALE),
                         pack_h2(v.z * WSCALE, v.w * WSCALE));
    *(uint2*)(dstB + z * WSZ + i) = o;
}

// ============================================================================
// mma.sync GEMM v6: C = A @ W^T + bias   (pure fp16, fp32 acc)
// CTA 64x128, 8 warps 2(m)x4(n), warp tile 32x32, BK=64, 3-stage pipeline.
// 64 MMAs per sync window (was 32) to amortize wait/barrier/issue overhead.
// Stage 24KB: A(8KB) | W(16KB).
// ============================================================================
#define GBK     64
#define G_A     0u
#define G_W     8192u
#define G_STAGE 24576u
#define GSM_BYTES (3 * 24576 + 128)   // 73856

__global__ __launch_bounds__(256, 2) void gemm_mma(
    const __half* __restrict__ Af,
    const __half* __restrict__ WfB,
    int wofs,
    const float* __restrict__ b0, const float* __restrict__ b1, const float* __restrict__ b2,
    float* __restrict__ Cf,
    __half* __restrict__ C0, __half* __restrict__ C1, __half* __restrict__ C2,
    float qs, int mode)
{
    extern __shared__ char dsm[];
    const uint32_t smbase = (smem_u32(dsm) + 127u) & ~127u;

    const int tid  = threadIdx.x;
    const int lane = tid & 31;
    const int wid  = tid >> 5;
    const int wm   = wid >> 2;      // 0..1
    const int wn   = wid & 3;       // 0..3
    const int row0 = blockIdx.y * 64;
    const int col0 = blockIdx.x * 128;
    const int z    = blockIdx.z;

    const __half* Wf = WfB + (size_t)(wofs + z) * WSZ;
    const float* bias = (z == 0) ? b0 : (z == 1) ? b1 : b2;
    __half* Ch = (z == 0) ? C0 : (z == 1) ? C1 : C2;
    const float scale = (z == 0) ? qs : 1.0f;

    const __half* srcs[2] = { Af + (size_t)row0 * D_, Wf + (size_t)col0 * D_ };

    // loader: 1536 granules/stage (A: 64rows x 8, W: 128rows x 8) = 6/thread
    // granule index within matrix: i = r*8 + kk*2 + g  (kk in 0..3, g in 0..1)
    int l_mat[6], l_r[6], l_koff[6];
    uint32_t l_dst[6];
    #pragma unroll
    for (int t = 0; t < 6; t++) {
        int idx = tid + t * 256;
        int mat, i;
        uint32_t base, chunk;
        if (idx < 512) { mat = 0; i = idx;       base = G_A; chunk = 2048u; }
        else           { mat = 1; i = idx - 512; base = G_W; chunk = 4096u; }
        int r = i >> 3, kk = (i >> 1) & 3, g = i & 1;
        int gsw = g ^ ((r >> 2) & 1);
        l_mat[t] = mat; l_r[t] = r; l_koff[t] = kk * 16 + g * 8;
        l_dst[t] = base + (uint32_t)kk * chunk + (uint32_t)r * 32u + (uint32_t)gsw * 16u;
    }

    auto issue = [&](int it2) {
        const uint32_t sb = smbase + (uint32_t)(it2 % 3) * G_STAGE;
        #pragma unroll
        for (int t = 0; t < 6; t++) {
            const __half* gp = srcs[l_mat[t]] +
                (size_t)l_r[t] * D_ + it2 * GBK + l_koff[t];
            CP_ASYNC16(sb + l_dst[t], gp);
        }
    };

    float acc[2][4][4];
    #pragma unroll
    for (int mi = 0; mi < 2; mi++)
        #pragma unroll
        for (int nj = 0; nj < 4; nj++)
            #pragma unroll
            for (int e = 0; e < 4; e++) acc[mi][nj][e] = 0.0f;

    const int lr = lane & 15;
    const int lg = lane >> 4;

    issue(0); CP_COMMIT();
    issue(1); CP_COMMIT();

    const int NIT = D_ / GBK;   // 16
    for (int it = 0; it < NIT; it++) {
        if (it < NIT - 1) { CP_WAIT1(); } else { CP_WAIT0(); }
        __syncthreads();
        if (it + 2 < NIT) { issue(it + 2); CP_COMMIT(); }

        const uint32_t stg = smbase + (uint32_t)(it % 3) * G_STAGE;
        #pragma unroll
        for (int kk = 0; kk < 4; kk++) {
            uint32_t af[2][4];
            #pragma unroll
            for (int mi = 0; mi < 2; mi++) {
                int r = wm * 32 + mi * 16 + lr;
                uint32_t off = (uint32_t)(kk * 2048 + r * 32 + ((lg ^ ((r >> 2) & 1)) * 16));
                LDSM_X4(af[mi], stg + G_A + off);
            }
            uint32_t bw[2][4];
            #pragma unroll
            for (int ni = 0; ni < 2; ni++) {
                int r = wn * 32 + ni * 16 + lr;
                uint32_t off = (uint32_t)(kk * 4096 + r * 32 + ((lg ^ ((r >> 2) & 1)) * 16));
                LDSM_X4(bw[ni], stg + G_W + off);
            }
            // 8 independent accumulators
            #pragma unroll
            for (int mi = 0; mi < 2; mi++)
                #pragma unroll
                for (int nj = 0; nj < 4; nj++) {
                    const int ni = nj >> 1, sel = nj & 1;
                    MMAH16816(acc[mi][nj], af[mi], bw[ni][sel], bw[ni][sel + 2]);
                }
        }
    }

    const int qr = lane >> 2;
    const int qc = (lane & 3) * 2;
    #pragma unroll
    for (int nj = 0; nj < 4; nj++) {
        const int c = col0 + wn * 32 + nj * 8 + qc;
        const float2 bv = *(const float2*)(bias + c);
        #pragma unroll
        for (int mi = 0; mi < 2; mi++) {
            const int r = row0 + wm * 32 + mi * 16 + qr;
            float v0 = (acc[mi][nj][0] * INV_WS + bv.x) * scale;
            float v1 = (acc[mi][nj][1] * INV_WS + bv.y) * scale;
            float v2 = (acc[mi][nj][2] * INV_WS + bv.x) * scale;
            float v3 = (acc[mi][nj][3] * INV_WS + bv.y) * scale;
            if (mode == 0) {
                *(float2*)(Cf + (size_t)r * D_ + c)       = make_float2(v0, v1);
                *(float2*)(Cf + (size_t)(r + 8) * D_ + c) = make_float2(v2, v3);
            } else {
                *(uint32_t*)(Ch + (size_t)r * D_ + c)       = pack_h2(v0, v1);
                *(uint32_t*)(Ch + (size_t)(r + 8) * D_ + c) = pack_h2(v2, v3);
            }
        }
    }
}

// ============================================================================
// Tensor-core flash attention v6 (causal), pure fp16 (fp32 acc).
// Softmax in base-2 domain (log2e folded into Q scale) with raw ex2.approx.
// CTA: 128 q-rows x 1 head, 8 warps, 64-key tiles, 2-stage double buffer.
// ============================================================================
#define FQ    128
#define FKT   64
#define F_K   0
#define F_V   8192
#define F_STG 16384
#define FSM_BYTES (2 * F_STG + 128)

__global__ __launch_bounds__(256, 2) void flash_mma(
    const __half* __restrict__ Qf,
    const __half* __restrict__ Kf, const __half* __restrict__ Vf,
    __half* __restrict__ Of)
{
    extern __shared__ char dsm[];
    const uint32_t smbase = (smem_u32(dsm) + 127u) & ~127u;

    const int tid  = threadIdx.x;
    const int lane = tid & 31;
    const int w    = tid >> 5;
    const int qb   = (int)gridDim.x - 1 - (int)blockIdx.x;  // big tiles first
    const int h    = blockIdx.y;
    const int b    = blockIdx.z;
    const int q0   = qb * FQ;

    // ---- stage Q (16KB) into stage0 temporarily
    #pragma unroll
    for (int t = 0; t < 4; t++) {
        int idx = tid + t * 256;
        int row = idx >> 3, g = idx & 7;
        const __half* src = Qf + (size_t)(b * S_ + q0 + row) * D_ + h * DK_ + g * 8;
        CP_ASYNC16(smbase + row * 128 + ((g ^ (row & 7)) << 4), src);
    }
    CP_COMMIT();
    CP_WAIT0();
    __syncthreads();

    uint32_t qa[4][4];
    const int qrow = w * 16 + (lane & 15);
    const int qlg  = lane >> 4;
    #pragma unroll
    for (int c = 0; c < 4; c++) {
        uint32_t off = qrow * 128 + ((c * 32 + qlg * 16) ^ ((qrow & 7) << 4));
        LDSM_X4(qa[c], smbase + off);
    }
    __syncthreads();   // stage0 free for KV

    auto load_kv = [&](int t) {
        const uint32_t stg = smbase + (uint32_t)(t & 1) * F_STG;
        #pragma unroll
        for (int u = 0; u < 4; u++) {
            int idx = tid + u * 256;
            int mat = idx >> 9;            // 0=K, 1=V
            int i   = idx & 511;
            int row = i >> 3, g = i & 7;
            const __half* src = (mat ? Vf : Kf) +
                (size_t)(b * S_ + t * FKT + row) * D_ + h * DK_ + g * 8;
            CP_ASYNC16(stg + mat * 8192 + row * 128 + ((g ^ (row & 7)) << 4), src);
        }
    };

    const int nkt = 2 * (qb + 1);
    load_kv(0); CP_COMMIT();
    if (nkt > 1) { load_kv(1); CP_COMMIT(); }

    float m_r[2] = {-1e30f, -1e30f};
    float l_r[2] = {0.0f, 0.0f};
    float oacc[8][4];
    #pragma unroll
    for (int j = 0; j < 8; j++)
        #pragma unroll
        for (int e = 0; e < 4; e++) oacc[j][e] = 0.0f;

    const int rg0 = q0 + w * 16 + (lane >> 2);

    for (int t = 0; t < nkt; t++) {
        if (t + 1 < nkt) { CP_WAIT1(); } else { CP_WAIT0(); }
        __syncthreads();

        const uint32_t stg = smbase + (uint32_t)(t & 1) * F_STG;

        // ---- scores S = Q K^T (log2-domain: Q pre-scaled by 1/8*log2e)
        float sacc[8][4];
        #pragma unroll
        for (int j = 0; j < 8; j++)
            #pragma unroll
            for (int e = 0; e < 4; e++) sacc[j][e] = 0.0f;

        #pragma unroll
        for (int c = 0; c < 4; c++) {
            #pragma unroll
            for (int ng = 0; ng < 4; ng++) {
                int row = ng * 16 + (lane & 15);
                int colb = c * 32 + qlg * 16;
                uint32_t off = row * 128 + (colb ^ ((row & 7) << 4));
                uint32_t kh[4];
                LDSM_X4(kh, stg + F_K + off);
                const int j0 = ng * 2, j1 = ng * 2 + 1;
                MMAH16816(sacc[j0], qa[c], kh[0], kh[2]);
                MMAH16816(sacc[j1], qa[c], kh[1], kh[3]);
            }
        }

        // ---- causal mask
        const int kt0 = t * FKT;
        if (kt0 + FKT - 1 > q0 + w * 16) {
            #pragma unroll
            for (int j = 0; j < 8; j++) {
                int kc = kt0 + j * 8 + (lane & 3) * 2;
                if (kc     > rg0)     sacc[j][0] = -1e30f;
                if (kc + 1 > rg0)     sacc[j][1] = -1e30f;
                if (kc     > rg0 + 8) sacc[j][2] = -1e30f;
                if (kc + 1 > rg0 + 8) sacc[j][3] = -1e30f;
            }
        }

        // ---- online softmax (base 2)
        float tm0 = -1e30f, tm1 = -1e30f;
        #pragma unroll
        for (int j = 0; j < 8; j++) {
            tm0 = fmaxf(tm0, fmaxf(sacc[j][0], sacc[j][1]));
            tm1 = fmaxf(tm1, fmaxf(sacc[j][2], sacc[j][3]));
        }
        tm0 = fmaxf(tm0, __shfl_xor_sync(0xffffffffu, tm0, 1));
        tm0 = fmaxf(tm0, __shfl_xor_sync(0xffffffffu, tm0, 2));
        tm1 = fmaxf(tm1, __shfl_xor_sync(0xffffffffu, tm1, 1));
        tm1 = fmaxf(tm1, __shfl_xor_sync(0xffffffffu, tm1, 2));

        float mn0 = fmaxf(m_r[0], tm0);
        float mn1 = fmaxf(m_r[1], tm1);
        float a0 = ex2f(m_r[0] - mn0);
        float a1 = ex2f(m_r[1] - mn1);
        m_r[0] = mn0; m_r[1] = mn1;

        float ps0 = 0.0f, ps1 = 0.0f;
        #pragma unroll
        for (int j = 0; j < 8; j++) {
            sacc[j][0] = ex2f(sacc[j][0] - mn0);
            sacc[j][1] = ex2f(sacc[j][1] - mn0);
            sacc[j][2] = ex2f(sacc[j][2] - mn1);
            sacc[j][3] = ex2f(sacc[j][3] - mn1);
            ps0 += sacc[j][0] + sacc[j][1];
            ps1 += sacc[j][2] + sacc[j][3];
        }
        ps0 += __shfl_xor_sync(0xffffffffu, ps0, 1);
        ps0 += __shfl_xor_sync(0xffffffffu, ps0, 2);
        ps1 += __shfl_xor_sync(0xffffffffu, ps1, 1);
        ps1 += __shfl_xor_sync(0xffffffffu, ps1, 2);
        l_r[0] = l_r[0] * a0 + ps0;
        l_r[1] = l_r[1] * a1 + ps1;

        #pragma unroll
        for (int j = 0; j < 8; j++) {
            oacc[j][0] *= a0; oacc[j][1] *= a0;
            oacc[j][2] *= a1; oacc[j][3] *= a1;
        }

        // ---- PV: oacc += P @ V
        #pragma unroll
        for (int tk = 0; tk < 4; tk++) {
            uint32_t pa[4];
            pa[0] = pack_h2(sacc[2*tk][0],   sacc[2*tk][1]);
            pa[1] = pack_h2(sacc[2*tk][2],   sacc[2*tk][3]);
            pa[2] = pack_h2(sacc[2*tk+1][0], sacc[2*tk+1][1]);
            pa[3] = pack_h2(sacc[2*tk+1][2], sacc[2*tk+1][3]);

            #pragma unroll
            for (int dp = 0; dp < 4; dp++) {
                int sub = lane >> 3, i8 = lane & 7;
                int row = tk * 16 + (sub & 1) * 8 + i8;
                int colb = dp * 32 + (sub >> 1) * 16;
                uint32_t off = row * 128 + (colb ^ ((row & 7) << 4));
                uint32_t vh[4];
                LDSM_X4_T(vh, stg + F_V + off);
                const int j0 = dp * 2, j1 = dp * 2 + 1;
                MMAH16816(oacc[j0], pa, vh[0], vh[1]);
                MMAH16816(oacc[j1], pa, vh[2], vh[3]);
            }
        }
        __syncthreads();          // all warps done with stage (t&1)
        if (t + 2 < nkt) { load_kv(t + 2); CP_COMMIT(); }
    }

    // ---- epilogue: normalize, fp16 out
    const float inv0 = 1.0f / l_r[0];
    const float inv1 = 1.0f / l_r[1];
    const size_t r0 = (size_t)(b * S_) + rg0;
    const size_t r1 = r0 + 8;
    #pragma unroll
    for (int j = 0; j < 8; j++) {
        int col = h * DK_ + j * 8 + (lane & 3) * 2;
        *(uint32_t*)(Of + r0 * D_ + col) = pack_h2(oacc[j][0] * inv0, oacc[j][1] * inv0);
        *(uint32_t*)(Of + r1 * D_ + col) = pack_h2(oacc[j][2] * inv1, oacc[j][3] * inv1);
    }
}

// ============================================================================
// Launch
// ============================================================================
extern "C" void kernel_launch(void* const* d_in, const int* in_sizes, int n_in,
                              void* d_out, int out_size)
{
    const float* X  = (const float*)d_in[0];
    const float* Wq = (const float*)d_in[1];
    const float* bq = (const float*)d_in[2];
    const float* Wk = (const float*)d_in[3];
    const float* bk = (const float*)d_in[4];
    const float* Wv = (const float*)d_in[5];
    const float* bv = (const float*)d_in[6];
    const float* Wo = (const float*)d_in[7];
    const float* bo = (const float*)d_in[8];
    float* out = (float*)d_out;

    __half *xf, *wf, *qf, *kf, *vf, *of;
    cudaGetSymbolAddress((void**)&xf, g_xf);
    cudaGetSymbolAddress((void**)&wf, g_wf);
    cudaGetSymbolAddress((void**)&qf, g_qf);
    cudaGetSymbolAddress((void**)&kf, g_kf);
    cudaGetSymbolAddress((void**)&vf, g_vf);
    cudaGetSymbolAddress((void**)&of, g_of);

    cudaFuncSetAttribute(gemm_mma, cudaFuncAttributeMaxDynamicSharedMemorySize, GSM_BYTES);
    cudaFuncSetAttribute(flash_mma, cudaFuncAttributeMaxDynamicSharedMemorySize, FSM_BYTES);

    const int nX = MTOT * D_;
    const int nW = D_ * D_;

    cvt_half<<<nX / 1024, 256>>>(X, xf, nX);
    cvt_w4<<<dim3(nW / 1024, 1, 4), 256>>>(Wq, Wk, Wv, Wo, wf);

    // fused QKV projection (z = 0:Q scaled by QSCALE, 1:K, 2:V)
    gemm_mma<<<dim3(8, 64, 3), 256, GSM_BYTES>>>(
        xf, wf, 0, bq, bk, bv,
        nullptr, qf, kf, vf, QSCALE, 1);

    flash_mma<<<dim3(S_ / FQ, H_, B_), 256, FSM_BYTES>>>(qf, kf, vf, of);

    // O projection (fp32 out)
    gemm_mma<<<dim3(8, 64, 1), 256, GSM_BYTES>>>(
        of, wf, 3, bo, bo, bo,
        out, nullptr, nullptr, nullptr, 1.0f, 0);
}

// round 11
// speedup vs baseline: 1.0155x; 1.0155x over previous
#include <cuda_runtime.h>
#include <cuda_fp16.h>
#include <math.h>
#include <stdint.h>

// Problem constants
#define B_   2
#define S_   2048
#define D_   1024
#define H_   16
#define DK_  64
#define MTOT (B_ * S_)   // 4096
#define WSZ  ((size_t)D_ * D_)

#define WSCALE   64.0f
#define INV_WS   (1.0f / 64.0f)
#define QSCALE   (0.125f * 1.44269504f)   // 1/sqrt(dk) * log2(e)  (softmax in base 2)

// fp16 buffers (all single precision fp16, fp32 accumulate in MMA)
__device__ __half g_xf [(size_t)MTOT * D_];     // X
__device__ __half g_wf [4][WSZ];                // 64*W
__device__ __half g_qf [(size_t)MTOT * D_];     // Q (pre-scaled by QSCALE)
__device__ __half g_kf [(size_t)MTOT * D_];
__device__ __half g_vf [(size_t)MTOT * D_];
__device__ __half g_of [(size_t)MTOT * D_];     // attn out

// ============================================================================
// PTX helpers (base sm_100-safe)
// ============================================================================
__device__ __forceinline__ uint32_t smem_u32(const void* p) {
    return (uint32_t)__cvta_generic_to_shared(p);
}

__device__ __forceinline__ float ex2f(float x) {
    float r;
    asm("ex2.approx.f32 %0, %1;" : "=f"(r) : "f"(x));
    return r;
}

#define CP_ASYNC16(dst, src) \
    asm volatile("cp.async.cg.shared.global [%0], [%1], 16;" :: "r"(dst), "l"(src))
#define CP_COMMIT() asm volatile("cp.async.commit_group;")
#define CP_WAIT2()  asm volatile("cp.async.wait_group 2;")
#define CP_WAIT1()  asm volatile("cp.async.wait_group 1;")
#define CP_WAIT0()  asm volatile("cp.async.wait_group 0;")

#define LDSM_X4(r, addr)                                                     \
    asm volatile("ldmatrix.sync.aligned.m8n8.x4.shared.b16 {%0,%1,%2,%3}, [%4];" \
                 : "=r"((r)[0]), "=r"((r)[1]), "=r"((r)[2]), "=r"((r)[3])    \
                 : "r"(addr))

#define LDSM_X4_T(r, addr)                                                   \
    asm volatile("ldmatrix.sync.aligned.m8n8.x4.trans.shared.b16 {%0,%1,%2,%3}, [%4];" \
                 : "=r"((r)[0]), "=r"((r)[1]), "=r"((r)[2]), "=r"((r)[3])    \
                 : "r"(addr))

#define MMAH16816(d, a, b0v, b1v)                                            \
    asm volatile("mma.sync.aligned.m16n8k16.row.col.f32.f16.f16.f32 "       \
                 "{%0,%1,%2,%3}, {%4,%5,%6,%7}, {%8,%9}, {%0,%1,%2,%3};"    \
                 : "+f"((d)[0]), "+f"((d)[1]), "+f"((d)[2]), "+f"((d)[3])   \
                 : "r"((a)[0]), "r"((a)[1]), "r"((a)[2]), "r"((a)[3]),      \
                   "r"(b0v), "r"(b1v))

__device__ __forceinline__ uint32_t pack_h2(float a, float b) {
    __half2 h = __floats2half2_rn(a, b);
    return *(uint32_t*)&h;
}

// ============================================================================
// conversion kernels
// ============================================================================
__global__ void cvt_half(const float* __restrict__ src, __half* __restrict__ dst, int n)
{
    int i = (blockIdx.x * blockDim.x + threadIdx.x) * 4;
    if (i >= n) return;
    float4 v = *(const float4*)(src + i);
    uint2 o = make_uint2(pack_h2(v.x, v.y), pack_h2(v.z, v.w));
    *(uint2*)(dst + i) = o;
}

// 4-weight convert with *WSCALE pre-scaling (z selects which W)
__global__ void cvt_w4(const float* __restrict__ W0, const float* __restrict__ W1,
                       const float* __restrict__ W2, const float* __restrict__ W3,
                       __half* __restrict__ dstB)
{
    const int z = blockIdx.z;
    const float* src = (z == 0) ? W0 : (z == 1) ? W1 : (z == 2) ? W2 : W3;
    int i = (blockIdx.x * blockDim.x + threadIdx.x) * 4;
    float4 v = *(const float4*)(src + i);
    uint2 o = make_uint2(pack_h2(v.x * WSCALE, v.y * WSCALE),
                         pack_h2(v.z * WSCALE, v.w * WSCALE));
    *(uint2*)(dstB + z * WSZ + i) = o;
}

// ============================================================================
// mma.sync GEMM v7: C = A @ W^T + bias   (pure fp16, fp32 acc)
// CTA 64x128, 8 warps 2(m)x4(n), warp tile 32x32, BK=32.
// 4-stage cp.async pipeline, lookahead 3 (~600 cyc cover > L2 latency).
// Stage 12KB: A(4KB) | W(8KB); 48KB total, 2 CTAs/SM.
// ============================================================================
#define GBK     32
#define G_A     0u
#define G_W     4096u
#define G_STAGE 12288u
#define GSM_BYTES (4 * 12288 + 128)   // 49280

__global__ __launch_bounds__(256, 2) void gemm_mma(
    const __half* __restrict__ Af,
    const __half* __restrict__ WfB,
    int wofs,
    const float* __restrict__ b0, const float* __restrict__ b1, const float* __restrict__ b2,
    float* __restrict__ Cf,
    __half* __restrict__ C0, __half* __restrict__ C1, __half* __restrict__ C2,
    float qs, int mode)
{
    extern __shared__ char dsm[];
    const uint32_t smbase = (smem_u32(dsm) + 127u) & ~127u;

    const int tid  = threadIdx.x;
    const int lane = tid & 31;
    const int wid  = tid >> 5;
    const int wm   = wid >> 2;      // 0..1
    const int wn   = wid & 3;       // 0..3
    const int row0 = blockIdx.y * 64;
    const int col0 = blockIdx.x * 128;
    const int z    = blockIdx.z;

    const __half* Wf = WfB + (size_t)(wofs + z) * WSZ;
    const float* bias = (z == 0) ? b0 : (z == 1) ? b1 : b2;
    __half* Ch = (z == 0) ? C0 : (z == 1) ? C1 : C2;
    const float scale = (z == 0) ? qs : 1.0f;

    const __half* srcs[2] = { Af + (size_t)row0 * D_, Wf + (size_t)col0 * D_ };

    // loader: 768 granules/stage (A:256, W:512) = 3/thread
    int l_mat[3], l_r[3], l_koff[3];
    uint32_t l_dst[3];
    #pragma unroll
    for (int t = 0; t < 3; t++) {
        int idx = tid + t * 256;
        int mat, i;
        uint32_t base, chunk;
        if (idx < 256) { mat = 0; i = idx;       base = G_A; chunk = 2048u; }
        else           { mat = 1; i = idx - 256; base = G_W; chunk = 4096u; }
        int r = i >> 2, kk = (i >> 1) & 1, g = i & 1;
        int gsw = g ^ ((r >> 2) & 1);
        l_mat[t] = mat; l_r[t] = r; l_koff[t] = kk * 16 + g * 8;
        l_dst[t] = base + (uint32_t)kk * chunk + (uint32_t)r * 32u + (uint32_t)gsw * 16u;
    }

    auto issue = [&](int it2) {
        const uint32_t sb = smbase + (uint32_t)(it2 & 3) * G_STAGE;
        #pragma unroll
        for (int t = 0; t < 3; t++) {
            const __half* gp = srcs[l_mat[t]] +
                (size_t)l_r[t] * D_ + it2 * GBK + l_koff[t];
            CP_ASYNC16(sb + l_dst[t], gp);
        }
    };

    float acc[2][4][4];
    #pragma unroll
    for (int mi = 0; mi < 2; mi++)
        #pragma unroll
        for (int nj = 0; nj < 4; nj++)
            #pragma unroll
            for (int e = 0; e < 4; e++) acc[mi][nj][e] = 0.0f;

    const int lr = lane & 15;
    const int lg = lane >> 4;

    issue(0); CP_COMMIT();
    issue(1); CP_COMMIT();
    issue(2); CP_COMMIT();

    const int NIT = D_ / GBK;   // 32
    for (int it = 0; it < NIT; it++) {
        if (it < NIT - 2)      { CP_WAIT2(); }
        else if (it < NIT - 1) { CP_WAIT1(); }
        else                   { CP_WAIT0(); }
        __syncthreads();
        if (it + 3 < NIT) { issue(it + 3); CP_COMMIT(); }

        const uint32_t stg = smbase + (uint32_t)(it & 3) * G_STAGE;
        #pragma unroll
        for (int kk = 0; kk < 2; kk++) {
            uint32_t af[2][4];
            #pragma unroll
            for (int mi = 0; mi < 2; mi++) {
                int r = wm * 32 + mi * 16 + lr;
                uint32_t off = (uint32_t)(kk * 2048 + r * 32 + ((lg ^ ((r >> 2) & 1)) * 16));
                LDSM_X4(af[mi], stg + G_A + off);
            }
            uint32_t bw[2][4];
            #pragma unroll
            for (int ni = 0; ni < 2; ni++) {
                int r = wn * 32 + ni * 16 + lr;
                uint32_t off = (uint32_t)(kk * 4096 + r * 32 + ((lg ^ ((r >> 2) & 1)) * 16));
                LDSM_X4(bw[ni], stg + G_W + off);
            }
            // 8 independent accumulators
            #pragma unroll
            for (int mi = 0; mi < 2; mi++)
                #pragma unroll
                for (int nj = 0; nj < 4; nj++) {
                    const int ni = nj >> 1, sel = nj & 1;
                    MMAH16816(acc[mi][nj], af[mi], bw[ni][sel], bw[ni][sel + 2]);
                }
        }
    }

    const int qr = lane >> 2;
    const int qc = (lane & 3) * 2;
    #pragma unroll
    for (int nj = 0; nj < 4; nj++) {
        const int c = col0 + wn * 32 + nj * 8 + qc;
        const float2 bv = *(const float2*)(bias + c);
        #pragma unroll
        for (int mi = 0; mi < 2; mi++) {
            const int r = row0 + wm * 32 + mi * 16 + qr;
            float v0 = (acc[mi][nj][0] * INV_WS + bv.x) * scale;
            float v1 = (acc[mi][nj][1] * INV_WS + bv.y) * scale;
            float v2 = (acc[mi][nj][2] * INV_WS + bv.x) * scale;
            float v3 = (acc[mi][nj][3] * INV_WS + bv.y) * scale;
            if (mode == 0) {
                *(float2*)(Cf + (size_t)r * D_ + c)       = make_float2(v0, v1);
                *(float2*)(Cf + (size_t)(r + 8) * D_ + c) = make_float2(v2, v3);
            } else {
                *(uint32_t*)(Ch + (size_t)r * D_ + c)       = pack_h2(v0, v1);
                *(uint32_t*)(Ch + (size_t)(r + 8) * D_ + c) = pack_h2(v2, v3);
            }
        }
    }
}

// ============================================================================
// Tensor-core flash attention v6 (causal), pure fp16 (fp32 acc).
// Softmax in base-2 domain (log2e folded into Q scale) with raw ex2.approx.
// CTA: 128 q-rows x 1 head, 8 warps, 64-key tiles, 2-stage double buffer.
// ============================================================================
#define FQ    128
#define FKT   64
#define F_K   0
#define F_V   8192
#define F_STG 16384
#define FSM_BYTES (2 * F_STG + 128)

__global__ __launch_bounds__(256, 2) void flash_mma(
    const __half* __restrict__ Qf,
    const __half* __restrict__ Kf, const __half* __restrict__ Vf,
    __half* __restrict__ Of)
{
    extern __shared__ char dsm[];
    const uint32_t smbase = (smem_u32(dsm) + 127u) & ~127u;

    const int tid  = threadIdx.x;
    const int lane = tid & 31;
    const int w    = tid >> 5;
    const int qb   = (int)gridDim.x - 1 - (int)blockIdx.x;  // big tiles first
    const int h    = blockIdx.y;
    const int b    = blockIdx.z;
    const int q0   = qb * FQ;

    // ---- stage Q (16KB) into stage0 temporarily
    #pragma unroll
    for (int t = 0; t < 4; t++) {
        int idx = tid + t * 256;
        int row = idx >> 3, g = idx & 7;
        const __half* src = Qf + (size_t)(b * S_ + q0 + row) * D_ + h * DK_ + g * 8;
        CP_ASYNC16(smbase + row * 128 + ((g ^ (row & 7)) << 4), src);
    }
    CP_COMMIT();
    CP_WAIT0();
    __syncthreads();

    uint32_t qa[4][4];
    const int qrow = w * 16 + (lane & 15);
    const int qlg  = lane >> 4;
    #pragma unroll
    for (int c = 0; c < 4; c++) {
        uint32_t off = qrow * 128 + ((c * 32 + qlg * 16) ^ ((qrow & 7) << 4));
        LDSM_X4(qa[c], smbase + off);
    }
    __syncthreads();   // stage0 free for KV

    auto load_kv = [&](int t) {
        const uint32_t stg = smbase + (uint32_t)(t & 1) * F_STG;
        #pragma unroll
        for (int u = 0; u < 4; u++) {
            int idx = tid + u * 256;
            int mat = idx >> 9;            // 0=K, 1=V
            int i   = idx & 511;
            int row = i >> 3, g = i & 7;
            const __half* src = (mat ? Vf : Kf) +
                (size_t)(b * S_ + t * FKT + row) * D_ + h * DK_ + g * 8;
            CP_ASYNC16(stg + mat * 8192 + row * 128 + ((g ^ (row & 7)) << 4), src);
        }
    };

    const int nkt = 2 * (qb + 1);
    load_kv(0); CP_COMMIT();
    if (nkt > 1) { load_kv(1); CP_COMMIT(); }

    float m_r[2] = {-1e30f, -1e30f};
    float l_r[2] = {0.0f, 0.0f};
    float oacc[8][4];
    #pragma unroll
    for (int j = 0; j < 8; j++)
        #pragma unroll
        for (int e = 0; e < 4; e++) oacc[j][e] = 0.0f;

    const int rg0 = q0 + w * 16 + (lane >> 2);

    for (int t = 0; t < nkt; t++) {
        if (t + 1 < nkt) { CP_WAIT1(); } else { CP_WAIT0(); }
        __syncthreads();

        const uint32_t stg = smbase + (uint32_t)(t & 1) * F_STG;

        // ---- scores S = Q K^T (log2-domain: Q pre-scaled by 1/8*log2e)
        float sacc[8][4];
        #pragma unroll
        for (int j = 0; j < 8; j++)
            #pragma unroll
            for (int e = 0; e < 4; e++) sacc[j][e] = 0.0f;

        #pragma unroll
        for (int c = 0; c < 4; c++) {
            #pragma unroll
            for (int ng = 0; ng < 4; ng++) {
                int row = ng * 16 + (lane & 15);
                int colb = c * 32 + qlg * 16;
                uint32_t off = row * 128 + (colb ^ ((row & 7) << 4));
                uint32_t kh[4];
                LDSM_X4(kh, stg + F_K + off);
                const int j0 = ng * 2, j1 = ng * 2 + 1;
                MMAH16816(sacc[j0], qa[c], kh[0], kh[2]);
                MMAH16816(sacc[j1], qa[c], kh[1], kh[3]);
            }
        }

        // ---- causal mask
        const int kt0 = t * FKT;
        if (kt0 + FKT - 1 > q0 + w * 16) {
            #pragma unroll
            for (int j = 0; j < 8; j++) {
                int kc = kt0 + j * 8 + (lane & 3) * 2;
                if (kc     > rg0)     sacc[j][0] = -1e30f;
                if (kc + 1 > rg0)     sacc[j][1] = -1e30f;
                if (kc     > rg0 + 8) sacc[j][2] = -1e30f;
                if (kc + 1 > rg0 + 8) sacc[j][3] = -1e30f;
            }
        }

        // ---- online softmax (base 2)
        float tm0 = -1e30f, tm1 = -1e30f;
        #pragma unroll
        for (int j = 0; j < 8; j++) {
            tm0 = fmaxf(tm0, fmaxf(sacc[j][0], sacc[j][1]));
            tm1 = fmaxf(tm1, fmaxf(sacc[j][2], sacc[j][3]));
        }
        tm0 = fmaxf(tm0, __shfl_xor_sync(0xffffffffu, tm0, 1));
        tm0 = fmaxf(tm0, __shfl_xor_sync(0xffffffffu, tm0, 2));
        tm1 = fmaxf(tm1, __shfl_xor_sync(0xffffffffu, tm1, 1));
        tm1 = fmaxf(tm1, __shfl_xor_sync(0xffffffffu, tm1, 2));

        float mn0 = fmaxf(m_r[0], tm0);
        float mn1 = fmaxf(m_r[1], tm1);
        float a0 = ex2f(m_r[0] - mn0);
        float a1 = ex2f(m_r[1] - mn1);
        m_r[0] = mn0; m_r[1] = mn1;

        float ps0 = 0.0f, ps1 = 0.0f;
        #pragma unroll
        for (int j = 0; j < 8; j++) {
            sacc[j][0] = ex2f(sacc[j][0] - mn0);
            sacc[j][1] = ex2f(sacc[j][1] - mn0);
            sacc[j][2] = ex2f(sacc[j][2] - mn1);
            sacc[j][3] = ex2f(sacc[j][3] - mn1);
            ps0 += sacc[j][0] + sacc[j][1];
            ps1 += sacc[j][2] + sacc[j][3];
        }
        ps0 += __shfl_xor_sync(0xffffffffu, ps0, 1);
        ps0 += __shfl_xor_sync(0xffffffffu, ps0, 2);
        ps1 += __shfl_xor_sync(0xffffffffu, ps1, 1);
        ps1 += __shfl_xor_sync(0xffffffffu, ps1, 2);
        l_r[0] = l_r[0] * a0 + ps0;
        l_r[1] = l_r[1] * a1 + ps1;

        #pragma unroll
        for (int j = 0; j < 8; j++) {
            oacc[j][0] *= a0; oacc[j][1] *= a0;
            oacc[j][2] *= a1; oacc[j][3] *= a1;
        }

        // ---- PV: oacc += P @ V
        #pragma unroll
        for (int tk = 0; tk < 4; tk++) {
            uint32_t pa[4];
            pa[0] = pack_h2(sacc[2*tk][0],   sacc[2*tk][1]);
            pa[1] = pack_h2(sacc[2*tk][2],   sacc[2*tk][3]);
            pa[2] = pack_h2(sacc[2*tk+1][0], sacc[2*tk+1][1]);
            pa[3] = pack_h2(sacc[2*tk+1][2], sacc[2*tk+1][3]);

            #pragma unroll
            for (int dp = 0; dp < 4; dp++) {
                int sub = lane >> 3, i8 = lane & 7;
                int row = tk * 16 + (sub & 1) * 8 + i8;
                int colb = dp * 32 + (sub >> 1) * 16;
                uint32_t off = row * 128 + (colb ^ ((row & 7) << 4));
                uint32_t vh[4];
                LDSM_X4_T(vh, stg + F_V + off);
                const int j0 = dp * 2, j1 = dp * 2 + 1;
                MMAH16816(oacc[j0], pa, vh[0], vh[1]);
                MMAH16816(oacc[j1], pa, vh[2], vh[3]);
            }
        }
        __syncthreads();          // all warps done with stage (t&1)
        if (t + 2 < nkt) { load_kv(t + 2); CP_COMMIT(); }
    }

    // ---- epilogue: normalize, fp16 out
    const float inv0 = 1.0f / l_r[0];
    const float inv1 = 1.0f / l_r[1];
    const size_t r0 = (size_t)(b * S_) + rg0;
    const size_t r1 = r0 + 8;
    #pragma unroll
    for (int j = 0; j < 8; j++) {
        int col = h * DK_ + j * 8 + (lane & 3) * 2;
        *(uint32_t*)(Of + r0 * D_ + col) = pack_h2(oacc[j][0] * inv0, oacc[j][1] * inv0);
        *(uint32_t*)(Of + r1 * D_ + col) = pack_h2(oacc[j][2] * inv1, oacc[j][3] * inv1);
    }
}

// ============================================================================
// Launch
// ============================================================================
extern "C" void kernel_launch(void* const* d_in, const int* in_sizes, int n_in,
                              void* d_out, int out_size)
{
    const float* X  = (const float*)d_in[0];
    const float* Wq = (const float*)d_in[1];
    const float* bq = (const float*)d_in[2];
    const float* Wk = (const float*)d_in[3];
    const float* bk = (const float*)d_in[4];
    const float* Wv = (const float*)d_in[5];
    const float* bv = (const float*)d_in[6];
    const float* Wo = (const float*)d_in[7];
    const float* bo = (const float*)d_in[8];
    float* out = (float*)d_out;

    __half *xf, *wf, *qf, *kf, *vf, *of;
    cudaGetSymbolAddress((void**)&xf, g_xf);
    cudaGetSymbolAddress((void**)&wf, g_wf);
    cudaGetSymbolAddress((void**)&qf, g_qf);
    cudaGetSymbolAddress((void**)&kf, g_kf);
    cudaGetSymbolAddress((void**)&vf, g_vf);
    cudaGetSymbolAddress((void**)&of, g_of);

    cudaFuncSetAttribute(gemm_mma, cudaFuncAttributeMaxDynamicSharedMemorySize, GSM_BYTES);
    cudaFuncSetAttribute(flash_mma, cudaFuncAttributeMaxDynamicSharedMemorySize, FSM_BYTES);

    const int nX = MTOT * D_;
    const int nW = D_ * D_;

    cvt_half<<<nX / 1024, 256>>>(X, xf, nX);
    cvt_w4<<<dim3(nW / 1024, 1, 4), 256>>>(Wq, Wk, Wv, Wo, wf);

    // fused QKV projection (z = 0:Q scaled by QSCALE, 1:K, 2:V)
    gemm_mma<<<dim3(8, 64, 3), 256, GSM_BYTES>>>(
        xf, wf, 0, bq, bk, bv,
        nullptr, qf, kf, vf, QSCALE, 1);

    flash_mma<<<dim3(S_ / FQ, H_, B_), 256, FSM_BYTES>>>(qf, kf, vf, of);

    // O projection (fp32 out)
    gemm_mma<<<dim3(8, 64, 1), 256, GSM_BYTES>>>(
        of, wf, 3, bo, bo, bo,
        out, nullptr, nullptr, nullptr, 1.0f, 0);
}

// round 12
// speedup vs baseline: 1.1494x; 1.1318x over previous
#include <cuda_runtime.h>
#include <cuda_fp16.h>
#include <math.h>
#include <stdint.h>

// Problem constants
#define B_   2
#define S_   2048
#define D_   1024
#define H_   16
#define DK_  64
#define MTOT (B_ * S_)   // 4096
#define WSZ  ((size_t)D_ * D_)

#define WSCALE   64.0f
#define INV_WS   (1.0f / 64.0f)
#define QSCALE   (0.125f * 1.44269504f)   // 1/sqrt(dk) * log2(e)  (softmax in base 2)

// fp16 buffers (all single precision fp16, fp32 accumulate in MMA)
__device__ __half g_xf [(size_t)MTOT * D_];     // X
__device__ __half g_wf [4][WSZ];                // 64*W
__device__ __half g_qf [(size_t)MTOT * D_];     // Q (pre-scaled by QSCALE)
__device__ __half g_kf [(size_t)MTOT * D_];
__device__ __half g_vf [(size_t)MTOT * D_];
__device__ __half g_of [(size_t)MTOT * D_];     // attn out

// ============================================================================
// PTX helpers (base sm_100-safe)
// ============================================================================
__device__ __forceinline__ uint32_t smem_u32(const void* p) {
    return (uint32_t)__cvta_generic_to_shared(p);
}

__device__ __forceinline__ float ex2f(float x) {
    float r;
    asm("ex2.approx.f32 %0, %1;" : "=f"(r) : "f"(x));
    return r;
}

#define CP_ASYNC16(dst, src) \
    asm volatile("cp.async.cg.shared.global [%0], [%1], 16;" :: "r"(dst), "l"(src))
#define CP_COMMIT() asm volatile("cp.async.commit_group;")
#define CP_WAIT1()  asm volatile("cp.async.wait_group 1;")
#define CP_WAIT0()  asm volatile("cp.async.wait_group 0;")

#define LDSM_X4(r, addr)                                                     \
    asm volatile("ldmatrix.sync.aligned.m8n8.x4.shared.b16 {%0,%1,%2,%3}, [%4];" \
                 : "=r"((r)[0]), "=r"((r)[1]), "=r"((r)[2]), "=r"((r)[3])    \
                 : "r"(addr))

#define LDSM_X4_T(r, addr)                                                   \
    asm volatile("ldmatrix.sync.aligned.m8n8.x4.trans.shared.b16 {%0,%1,%2,%3}, [%4];" \
                 : "=r"((r)[0]), "=r"((r)[1]), "=r"((r)[2]), "=r"((r)[3])    \
                 : "r"(addr))

#define MMAH16816(d, a, b0v, b1v)                                            \
    asm volatile("mma.sync.aligned.m16n8k16.row.col.f32.f16.f16.f32 "       \
                 "{%0,%1,%2,%3}, {%4,%5,%6,%7}, {%8,%9}, {%0,%1,%2,%3};"    \
                 : "+f"((d)[0]), "+f"((d)[1]), "+f"((d)[2]), "+f"((d)[3])   \
                 : "r"((a)[0]), "r"((a)[1]), "r"((a)[2]), "r"((a)[3]),      \
                   "r"(b0v), "r"(b1v))

__device__ __forceinline__ uint32_t pack_h2(float a, float b) {
    __half2 h = __floats2half2_rn(a, b);
    return *(uint32_t*)&h;
}

// ============================================================================
// fused conversion kernel: one launch converts X and all 4 weights.
// blocks [0, 4096)        -> X  (scale 1)
// blocks [4096, 8192)     -> W0..W3 (scale WSCALE), 1024 blocks each
// ============================================================================
__global__ void cvt_all(const float* __restrict__ X,
                        const float* __restrict__ W0, const float* __restrict__ W1,
                        const float* __restrict__ W2, const float* __restrict__ W3,
                        __half* __restrict__ xf, __half* __restrict__ wf)
{
    const int blk = blockIdx.x;
    const float* src;
    __half* dst;
    float sc;
    int i;
    if (blk < 4096) {
        src = X; dst = xf; sc = 1.0f;
        i = (blk * 256 + threadIdx.x) * 4;
    } else {
        const int z = (blk - 4096) >> 10;
        const int j = (blk - 4096) & 1023;
        src = (z == 0) ? W0 : (z == 1) ? W1 : (z == 2) ? W2 : W3;
        dst = wf + (size_t)z * WSZ;
        sc = WSCALE;
        i = (j * 256 + threadIdx.x) * 4;
    }
    float4 v = *(const float4*)(src + i);
    uint2 o = make_uint2(pack_h2(v.x * sc, v.y * sc), pack_h2(v.z * sc, v.w * sc));
    *(uint2*)(dst + i) = o;
}

// ============================================================================
// mma.sync GEMM (R9 config, byte-exact): C = A @ W^T + bias (pure fp16, fp32 acc)
// CTA 64x128, 8 warps 2(m)x4(n), warp tile 32x32, BK=32, 3-stage pipeline.
// Stage 12KB: A(4KB) | W(8KB).
// ============================================================================
#define GBK     32
#define G_A     0u
#define G_W     4096u
#define G_STAGE 12288u
#define GSM_BYTES (3 * 12288 + 128)

__global__ __launch_bounds__(256, 2) void gemm_mma(
    const __half* __restrict__ Af,
    const __half* __restrict__ WfB,
    int wofs,
    const float* __restrict__ b0, const float* __restrict__ b1, const float* __restrict__ b2,
    float* __restrict__ Cf,
    __half* __restrict__ C0, __half* __restrict__ C1, __half* __restrict__ C2,
    float qs, int mode)
{
    extern __shared__ char dsm[];
    const uint32_t smbase = (smem_u32(dsm) + 127u) & ~127u;

    const int tid  = threadIdx.x;
    const int lane = tid & 31;
    const int wid  = tid >> 5;
    const int wm   = wid >> 2;      // 0..1
    const int wn   = wid & 3;       // 0..3
    const int row0 = blockIdx.y * 64;
    const int col0 = blockIdx.x * 128;
    const int z    = blockIdx.z;

    const __half* Wf = WfB + (size_t)(wofs + z) * WSZ;
    const float* bias = (z == 0) ? b0 : (z == 1) ? b1 : b2;
    __half* Ch = (z == 0) ? C0 : (z == 1) ? C1 : C2;
    const float scale = (z == 0) ? qs : 1.0f;

    const __half* srcs[2] = { Af + (size_t)row0 * D_, Wf + (size_t)col0 * D_ };

    // loader: 768 granules/stage (A:256, W:512) = 3/thread
    int l_mat[3], l_r[3], l_koff[3];
    uint32_t l_dst[3];
    #pragma unroll
    for (int t = 0; t < 3; t++) {
        int idx = tid + t * 256;
        int mat, i;
        uint32_t base, chunk;
        if (idx < 256) { mat = 0; i = idx;       base = G_A; chunk = 2048u; }
        else           { mat = 1; i = idx - 256; base = G_W; chunk = 4096u; }
        int r = i >> 2, kk = (i >> 1) & 1, g = i & 1;
        int gsw = g ^ ((r >> 2) & 1);
        l_mat[t] = mat; l_r[t] = r; l_koff[t] = kk * 16 + g * 8;
        l_dst[t] = base + (uint32_t)kk * chunk + (uint32_t)r * 32u + (uint32_t)gsw * 16u;
    }

    auto issue = [&](int it2) {
        const uint32_t sb = smbase + (uint32_t)(it2 % 3) * G_STAGE;
        #pragma unroll
        for (int t = 0; t < 3; t++) {
            const __half* gp = srcs[l_mat[t]] +
                (size_t)l_r[t] * D_ + it2 * GBK + l_koff[t];
            CP_ASYNC16(sb + l_dst[t], gp);
        }
    };

    float acc[2][4][4];
    #pragma unroll
    for (int mi = 0; mi < 2; mi++)
        #pragma unroll
        for (int nj = 0; nj < 4; nj++)
            #pragma unroll
            for (int e = 0; e < 4; e++) acc[mi][nj][e] = 0.0f;

    const int lr = lane & 15;
    const int lg = lane >> 4;

    issue(0); CP_COMMIT();
    issue(1); CP_COMMIT();

    const int NIT = D_ / GBK;   // 32
    for (int it = 0; it < NIT; it++) {
        if (it < NIT - 1) { CP_WAIT1(); } else { CP_WAIT0(); }
        __syncthreads();
        if (it + 2 < NIT) { issue(it + 2); CP_COMMIT(); }

        const uint32_t stg = smbase + (uint32_t)(it % 3) * G_STAGE;
        #pragma unroll
        for (int kk = 0; kk < 2; kk++) {
            uint32_t af[2][4];
            #pragma unroll
            for (int mi = 0; mi < 2; mi++) {
                int r = wm * 32 + mi * 16 + lr;
                uint32_t off = (uint32_t)(kk * 2048 + r * 32 + ((lg ^ ((r >> 2) & 1)) * 16));
                LDSM_X4(af[mi], stg + G_A + off);
            }
            uint32_t bw[2][4];
            #pragma unroll
            for (int ni = 0; ni < 2; ni++) {
                int r = wn * 32 + ni * 16 + lr;
                uint32_t off = (uint32_t)(kk * 4096 + r * 32 + ((lg ^ ((r >> 2) & 1)) * 16));
                LDSM_X4(bw[ni], stg + G_W + off);
            }
            // 8 independent accumulators
            #pragma unroll
            for (int mi = 0; mi < 2; mi++)
                #pragma unroll
                for (int nj = 0; nj < 4; nj++) {
                    const int ni = nj >> 1, sel = nj & 1;
                    MMAH16816(acc[mi][nj], af[mi], bw[ni][sel], bw[ni][sel + 2]);
                }
        }
    }

    const int qr = lane >> 2;
    const int qc = (lane & 3) * 2;
    #pragma unroll
    for (int nj = 0; nj < 4; nj++) {
        const int c = col0 + wn * 32 + nj * 8 + qc;
        const float2 bv = *(const float2*)(bias + c);
        #pragma unroll
        for (int mi = 0; mi < 2; mi++) {
            const int r = row0 + wm * 32 + mi * 16 + qr;
            float v0 = (acc[mi][nj][0] * INV_WS + bv.x) * scale;
            float v1 = (acc[mi][nj][1] * INV_WS + bv.y) * scale;
            float v2 = (acc[mi][nj][2] * INV_WS + bv.x) * scale;
            float v3 = (acc[mi][nj][3] * INV_WS + bv.y) * scale;
            if (mode == 0) {
                *(float2*)(Cf + (size_t)r * D_ + c)       = make_float2(v0, v1);
                *(float2*)(Cf + (size_t)(r + 8) * D_ + c) = make_float2(v2, v3);
            } else {
                *(uint32_t*)(Ch + (size_t)r * D_ + c)       = pack_h2(v0, v1);
                *(uint32_t*)(Ch + (size_t)(r + 8) * D_ + c) = pack_h2(v2, v3);
            }
        }
    }
}

// ============================================================================
// Tensor-core flash attention (R11 config, byte-exact): causal, pure fp16.
// Softmax in base-2 domain (log2e folded into Q scale) with raw ex2.approx.
// CTA: 128 q-rows x 1 head, 8 warps, 64-key tiles, 2-stage double buffer.
// ============================================================================
#define FQ    128
#define FKT   64
#define F_K   0
#define F_V   8192
#define F_STG 16384
#define FSM_BYTES (2 * F_STG + 128)

__global__ __launch_bounds__(256, 2) void flash_mma(
    const __half* __restrict__ Qf,
    const __half* __restrict__ Kf, const __half* __restrict__ Vf,
    __half* __restrict__ Of)
{
    extern __shared__ char dsm[];
    const uint32_t smbase = (smem_u32(dsm) + 127u) & ~127u;

    const int tid  = threadIdx.x;
    const int lane = tid & 31;
    const int w    = tid >> 5;
    const int qb   = (int)gridDim.x - 1 - (int)blockIdx.x;  // big tiles first
    const int h    = blockIdx.y;
    const int b    = blockIdx.z;
    const int q0   = qb * FQ;

    // ---- stage Q (16KB) into stage0 temporarily
    #pragma unroll
    for (int t = 0; t < 4; t++) {
        int idx = tid + t * 256;
        int row = idx >> 3, g = idx & 7;
        const __half* src = Qf + (size_t)(b * S_ + q0 + row) * D_ + h * DK_ + g * 8;
        CP_ASYNC16(smbase + row * 128 + ((g ^ (row & 7)) << 4), src);
    }
    CP_COMMIT();
    CP_WAIT0();
    __syncthreads();

    uint32_t qa[4][4];
    const int qrow = w * 16 + (lane & 15);
    const int qlg  = lane >> 4;
    #pragma unroll
    for (int c = 0; c < 4; c++) {
        uint32_t off = qrow * 128 + ((c * 32 + qlg * 16) ^ ((qrow & 7) << 4));
        LDSM_X4(qa[c], smbase + off);
    }
    __syncthreads();   // stage0 free for KV

    auto load_kv = [&](int t) {
        const uint32_t stg = smbase + (uint32_t)(t & 1) * F_STG;
        #pragma unroll
        for (int u = 0; u < 4; u++) {
            int idx = tid + u * 256;
            int mat = idx >> 9;            // 0=K, 1=V
            int i   = idx & 511;
            int row = i >> 3, g = i & 7;
            const __half* src = (mat ? Vf : Kf) +
                (size_t)(b * S_ + t * FKT + row) * D_ + h * DK_ + g * 8;
            CP_ASYNC16(stg + mat * 8192 + row * 128 + ((g ^ (row & 7)) << 4), src);
        }
    };

    const int nkt = 2 * (qb + 1);
    load_kv(0); CP_COMMIT();
    if (nkt > 1) { load_kv(1); CP_COMMIT(); }

    float m_r[2] = {-1e30f, -1e30f};
    float l_r[2] = {0.0f, 0.0f};
    float oacc[8][4];
    #pragma unroll
    for (int j = 0; j < 8; j++)
        #pragma unroll
        for (int e = 0; e < 4; e++) oacc[j][e] = 0.0f;

    const int rg0 = q0 + w * 16 + (lane >> 2);

    for (int t = 0; t < nkt; t++) {
        if (t + 1 < nkt) { CP_WAIT1(); } else { CP_WAIT0(); }
        __syncthreads();

        const uint32_t stg = smbase + (uint32_t)(t & 1) * F_STG;

        // ---- scores S = Q K^T (log2-domain: Q pre-scaled by 1/8*log2e)
        float sacc[8][4];
        #pragma unroll
        for (int j = 0; j < 8; j++)
            #pragma unroll
            for (int e = 0; e < 4; e++) sacc[j][e] = 0.0f;

        #pragma unroll
        for (int c = 0; c < 4; c++) {
            #pragma unroll
            for (int ng = 0; ng < 4; ng++) {
                int row = ng * 16 + (lane & 15);
                int colb = c * 32 + qlg * 16;
                uint32_t off = row * 128 + (colb ^ ((row & 7) << 4));
                uint32_t kh[4];
                LDSM_X4(kh, stg + F_K + off);
                const int j0 = ng * 2, j1 = ng * 2 + 1;
                MMAH16816(sacc[j0], qa[c], kh[0], kh[2]);
                MMAH16816(sacc[j1], qa[c], kh[1], kh[3]);
            }
        }

        // ---- causal mask
        const int kt0 = t * FKT;
        if (kt0 + FKT - 1 > q0 + w * 16) {
            #pragma unroll
            for (int j = 0; j < 8; j++) {
                int kc = kt0 + j * 8 + (lane & 3) * 2;
                if (kc     > rg0)     sacc[j][0] = -1e30f;
                if (kc + 1 > rg0)     sacc[j][1] = -1e30f;
                if (kc     > rg0 + 8) sacc[j][2] = -1e30f;
                if (kc + 1 > rg0 + 8) sacc[j][3] = -1e30f;
            }
        }

        // ---- online softmax (base 2)
        float tm0 = -1e30f, tm1 = -1e30f;
        #pragma unroll
        for (int j = 0; j < 8; j++) {
            tm0 = fmaxf(tm0, fmaxf(sacc[j][0], sacc[j][1]));
            tm1 = fmaxf(tm1, fmaxf(sacc[j][2], sacc[j][3]));
        }
        tm0 = fmaxf(tm0, __shfl_xor_sync(0xffffffffu, tm0, 1));
        tm0 = fmaxf(tm0, __shfl_xor_sync(0xffffffffu, tm0, 2));
        tm1 = fmaxf(tm1, __shfl_xor_sync(0xffffffffu, tm1, 1));
        tm1 = fmaxf(tm1, __shfl_xor_sync(0xffffffffu, tm1, 2));

        float mn0 = fmaxf(m_r[0], tm0);
        float mn1 = fmaxf(m_r[1], tm1);
        float a0 = ex2f(m_r[0] - mn0);
        float a1 = ex2f(m_r[1] - mn1);
        m_r[0] = mn0; m_r[1] = mn1;

        float ps0 = 0.0f, ps1 = 0.0f;
        #pragma unroll
        for (int j = 0; j < 8; j++) {
            sacc[j][0] = ex2f(sacc[j][0] - mn0);
            sacc[j][1] = ex2f(sacc[j][1] - mn0);
            sacc[j][2] = ex2f(sacc[j][2] - mn1);
            sacc[j][3] = ex2f(sacc[j][3] - mn1);
            ps0 += sacc[j][0] + sacc[j][1];
            ps1 += sacc[j][2] + sacc[j][3];
        }
        ps0 += __shfl_xor_sync(0xffffffffu, ps0, 1);
        ps0 += __shfl_xor_sync(0xffffffffu, ps0, 2);
        ps1 += __shfl_xor_sync(0xffffffffu, ps1, 1);
        ps1 += __shfl_xor_sync(0xffffffffu, ps1, 2);
        l_r[0] = l_r[0] * a0 + ps0;
        l_r[1] = l_r[1] * a1 + ps1;

        #pragma unroll
        for (int j = 0; j < 8; j++) {
            oacc[j][0] *= a0; oacc[j][1] *= a0;
            oacc[j][2] *= a1; oacc[j][3] *= a1;
        }

        // ---- PV: oacc += P @ V
        #pragma unroll
        for (int tk = 0; tk < 4; tk++) {
            uint32_t pa[4];
            pa[0] = pack_h2(sacc[2*tk][0],   sacc[2*tk][1]);
            pa[1] = pack_h2(sacc[2*tk][2],   sacc[2*tk][3]);
            pa[2] = pack_h2(sacc[2*tk+1][0], sacc[2*tk+1][1]);
            pa[3] = pack_h2(sacc[2*tk+1][2], sacc[2*tk+1][3]);

            #pragma unroll
            for (int dp = 0; dp < 4; dp++) {
                int sub = lane >> 3, i8 = lane & 7;
                int row = tk * 16 + (sub & 1) * 8 + i8;
                int colb = dp * 32 + (sub >> 1) * 16;
                uint32_t off = row * 128 + (colb ^ ((row & 7) << 4));
                uint32_t vh[4];
                LDSM_X4_T(vh, stg + F_V + off);
                const int j0 = dp * 2, j1 = dp * 2 + 1;
                MMAH16816(oacc[j0], pa, vh[0], vh[1]);
                MMAH16816(oacc[j1], pa, vh[2], vh[3]);
            }
        }
        __syncthreads();          // all warps done with stage (t&1)
        if (t + 2 < nkt) { load_kv(t + 2); CP_COMMIT(); }
    }

    // ---- epilogue: normalize, fp16 out
    const float inv0 = 1.0f / l_r[0];
    const float inv1 = 1.0f / l_r[1];
    const size_t r0 = (size_t)(b * S_) + rg0;
    const size_t r1 = r0 + 8;
    #pragma unroll
    for (int j = 0; j < 8; j++) {
        int col = h * DK_ + j * 8 + (lane & 3) * 2;
        *(uint32_t*)(Of + r0 * D_ + col) = pack_h2(oacc[j][0] * inv0, oacc[j][1] * inv0);
        *(uint32_t*)(Of + r1 * D_ + col) = pack_h2(oacc[j][2] * inv1, oacc[j][3] * inv1);
    }
}

// ============================================================================
// Launch
// ============================================================================
extern "C" void kernel_launch(void* const* d_in, const int* in_sizes, int n_in,
                              void* d_out, int out_size)
{
    const float* X  = (const float*)d_in[0];
    const float* Wq = (const float*)d_in[1];
    const float* bq = (const float*)d_in[2];
    const float* Wk = (const float*)d_in[3];
    const float* bk = (const float*)d_in[4];
    const float* Wv = (const float*)d_in[5];
    const float* bv = (const float*)d_in[6];
    const float* Wo = (const float*)d_in[7];
    const float* bo = (const float*)d_in[8];
    float* out = (float*)d_out;

    __half *xf, *wf, *qf, *kf, *vf, *of;
    cudaGetSymbolAddress((void**)&xf, g_xf);
    cudaGetSymbolAddress((void**)&wf, g_wf);
    cudaGetSymbolAddress((void**)&qf, g_qf);
    cudaGetSymbolAddress((void**)&kf, g_kf);
    cudaGetSymbolAddress((void**)&vf, g_vf);
    cudaGetSymbolAddress((void**)&of, g_of);

    cudaFuncSetAttribute(gemm_mma, cudaFuncAttributeMaxDynamicSharedMemorySize, GSM_BYTES);
    cudaFuncSetAttribute(flash_mma, cudaFuncAttributeMaxDynamicSharedMemorySize, FSM_BYTES);

    // fused conversion: X + 4 weights in one launch
    cvt_all<<<8192, 256>>>(X, Wq, Wk, Wv, Wo, xf, wf);

    // fused QKV projection (z = 0:Q scaled by QSCALE, 1:K, 2:V)
    gemm_mma<<<dim3(8, 64, 3), 256, GSM_BYTES>>>(
        xf, wf, 0, bq, bk, bv,
        nullptr, qf, kf, vf, QSCALE, 1);

    flash_mma<<<dim3(S_ / FQ, H_, B_), 256, FSM_BYTES>>>(qf, kf, vf, of);

    // O projection (fp32 out)
    gemm_mma<<<dim3(8, 64, 1), 256, GSM_BYTES>>>(
        of, wf, 3, bo, bo, bo,
        out, nullptr, nullptr, nullptr, 1.0f, 0);
}